// round 2
// baseline (speedup 1.0000x reference)
#include <cuda_runtime.h>

#define BS   256
#define FTN  8
#define ATN  264   // BS + FTN
#define NDIM 512

// Scratch (no allocations allowed): logits [256 x 264], per-row/col lse-diag terms
__device__ float g_logits[BS * ATN];
__device__ float g_lse[2 * BS];

// ---------------------------------------------------------------------------
// Kernel 1: one warp per (b, a) row.
//   logits[b,a] = exp(logit_scale) * dot(img[b,a], text) / (||img[b,a]|| * ||text||)
//   text = rand[a]               if a < 256
//        = false[b*8 + (a-256)]  otherwise
// Normalization is folded into the dot (never materialize normalized tensors).
// ---------------------------------------------------------------------------
__global__ __launch_bounds__(256) void cl_dot_kernel(
    const float* __restrict__ img,
    const float* __restrict__ rand_t,
    const float* __restrict__ false_t,
    const float* __restrict__ logit_scale)
{
    int gwarp = (blockIdx.x * blockDim.x + threadIdx.x) >> 5;
    int lane  = threadIdx.x & 31;
    if (gwarp >= BS * ATN) return;

    int b = gwarp / ATN;
    int a = gwarp - b * ATN;

    const float4* ip = (const float4*)(img + (size_t)gwarp * NDIM);
    const float*  tbase = (a < BS)
        ? (rand_t + (size_t)a * NDIM)
        : (false_t + ((size_t)b * FTN + (a - BS)) * NDIM);
    const float4* tp = (const float4*)tbase;

    float dot = 0.f, in2 = 0.f, tn2 = 0.f;
    #pragma unroll
    for (int i = 0; i < 4; i++) {            // 4 x float4 per lane = 512 floats/warp
        float4 x = ip[lane + 32 * i];
        float4 t = tp[lane + 32 * i];
        dot += x.x * t.x + x.y * t.y + x.z * t.z + x.w * t.w;
        in2 += x.x * x.x + x.y * x.y + x.z * x.z + x.w * x.w;
        tn2 += t.x * t.x + t.y * t.y + t.z * t.z + t.w * t.w;
    }
    #pragma unroll
    for (int o = 16; o > 0; o >>= 1) {
        dot += __shfl_xor_sync(0xffffffffu, dot, o);
        in2 += __shfl_xor_sync(0xffffffffu, in2, o);
        tn2 += __shfl_xor_sync(0xffffffffu, tn2, o);
    }
    if (lane == 0) {
        float scale = expf(logit_scale[0]);
        g_logits[gwarp] = scale * dot * rsqrtf(in2 * tn2);
    }
}

// ---------------------------------------------------------------------------
// Kernel 2: 512 blocks x 256 threads.
//   block b in [0,256):   image CE term  lse(logits[b, 0:264]) - logits[b,b]
//   block 256+a:          text  CE term  lse(logits[0:256, a]) - logits[a,a]
// Fixed-order shared-memory tree reductions (deterministic).
// ---------------------------------------------------------------------------
__global__ __launch_bounds__(256) void cl_lse_kernel()
{
    __shared__ float sd[256];
    int bid = blockIdx.x;
    int t   = threadIdx.x;

    float v1 = -1e30f, v2 = -1e30f;
    float diag;
    if (bid < BS) {
        int b = bid;
        v1 = g_logits[b * ATN + t];
        if (t < ATN - BS) v2 = g_logits[b * ATN + BS + t];
        diag = g_logits[b * ATN + b];
    } else {
        int a = bid - BS;
        v1 = g_logits[t * ATN + a];
        diag = g_logits[a * ATN + a];
    }

    // block max
    sd[t] = fmaxf(v1, v2);
    __syncthreads();
    #pragma unroll
    for (int s = 128; s > 0; s >>= 1) {
        if (t < s) sd[t] = fmaxf(sd[t], sd[t + s]);
        __syncthreads();
    }
    float m = sd[0];
    __syncthreads();

    // block sum of exp
    sd[t] = expf(v1 - m) + expf(v2 - m);   // exp(-1e30 - m) == 0 for inactive slots
    __syncthreads();
    #pragma unroll
    for (int s = 128; s > 0; s >>= 1) {
        if (t < s) sd[t] += sd[t + s];
        __syncthreads();
    }
    if (t == 0) g_lse[bid] = m + logf(sd[0]) - diag;
}

// ---------------------------------------------------------------------------
// Kernel 3: final scalar.  loss = (mean_img + mean_text)/2 = sum(g_lse)/512
// ---------------------------------------------------------------------------
__global__ __launch_bounds__(256) void cl_final_kernel(float* __restrict__ out)
{
    __shared__ float sd[256];
    int t = threadIdx.x;
    sd[t] = g_lse[t] + g_lse[t + BS];
    __syncthreads();
    #pragma unroll
    for (int s = 128; s > 0; s >>= 1) {
        if (t < s) sd[t] += sd[t + s];
        __syncthreads();
    }
    if (t == 0) out[0] = sd[0] * (1.0f / (2.0f * BS));
}

extern "C" void kernel_launch(void* const* d_in, const int* in_sizes, int n_in,
                              void* d_out, int out_size)
{
    const float* img     = (const float*)d_in[0];  // [256, 264, 512]
    const float* rand_t  = (const float*)d_in[1];  // [256, 512]
    const float* false_t = (const float*)d_in[2];  // [2048, 512]
    const float* lscale  = (const float*)d_in[3];  // [1]
    float* out = (float*)d_out;

    // 67584 warps, 8 warps/block -> 8448 blocks
    const int nwarps = BS * ATN;
    const int tpb = 256;
    const int nblocks = (nwarps * 32 + tpb - 1) / tpb;

    cl_dot_kernel<<<nblocks, tpb>>>(img, rand_t, false_t, lscale);
    cl_lse_kernel<<<2 * BS, 256>>>();
    cl_final_kernel<<<1, 256>>>(out);
}

// round 4
// speedup vs baseline: 1.1171x; 1.1171x over previous
#include <cuda_runtime.h>

#define BS   256
#define FTN  8
#define ATN  264   // BS + FTN
#define NDIM 512

// Scratch (no allocations allowed): logits [256 x 264]
__device__ float g_logits[BS * ATN];

__device__ __forceinline__ void acc3(const float4& x, const float4& t,
                                     float& dot, float& in2, float& tn2)
{
    dot += x.x * t.x + x.y * t.y + x.z * t.z + x.w * t.w;
    in2 += x.x * x.x + x.y * x.y + x.z * x.z + x.w * x.w;
    tn2 += t.x * t.x + t.y * t.y + t.z * t.z + t.w * t.w;
}

// ---------------------------------------------------------------------------
// Kernel 1: one warp per (b, a) row.
//   logits[b,a] = exp(logit_scale) * dot(img[b,a], text) / (||img|| * ||text||)
// All 8 LDG.128s issued up-front into live registers (MLP=8 per warp).
// Image stream uses .cs (evict-first) to keep text rows resident in L2.
// Thread (0,0) also zeroes out[0] for kernel 2's atomic accumulation.
// ---------------------------------------------------------------------------
__global__ __launch_bounds__(256) void cl_dot_kernel(
    const float* __restrict__ img,
    const float* __restrict__ rand_t,
    const float* __restrict__ false_t,
    const float* __restrict__ logit_scale,
    float* __restrict__ out)
{
    int gwarp = (blockIdx.x * blockDim.x + threadIdx.x) >> 5;
    int lane  = threadIdx.x & 31;
    if (blockIdx.x == 0 && threadIdx.x == 0) out[0] = 0.0f;
    if (gwarp >= BS * ATN) return;

    int b = gwarp / ATN;
    int a = gwarp - b * ATN;

    const float4* ip = (const float4*)(img + (size_t)gwarp * NDIM);
    const float*  tbase = (a < BS)
        ? (rand_t + (size_t)a * NDIM)
        : (false_t + ((size_t)b * FTN + (a - BS)) * NDIM);
    const float4* tp = (const float4*)tbase;

    // Front-batched loads: 8 independent LDG.128 in flight.
    float4 x0 = __ldcs(ip + lane);
    float4 x1 = __ldcs(ip + lane + 32);
    float4 x2 = __ldcs(ip + lane + 64);
    float4 x3 = __ldcs(ip + lane + 96);
    float4 t0 = __ldg(tp + lane);
    float4 t1 = __ldg(tp + lane + 32);
    float4 t2 = __ldg(tp + lane + 64);
    float4 t3 = __ldg(tp + lane + 96);

    float dot = 0.f, in2 = 0.f, tn2 = 0.f;
    acc3(x0, t0, dot, in2, tn2);
    acc3(x1, t1, dot, in2, tn2);
    acc3(x2, t2, dot, in2, tn2);
    acc3(x3, t3, dot, in2, tn2);

    #pragma unroll
    for (int o = 16; o > 0; o >>= 1) {
        dot += __shfl_xor_sync(0xffffffffu, dot, o);
        in2 += __shfl_xor_sync(0xffffffffu, in2, o);
        tn2 += __shfl_xor_sync(0xffffffffu, tn2, o);
    }
    if (lane == 0) {
        float scale = expf(logit_scale[0]);
        g_logits[gwarp] = scale * dot * rsqrtf(in2 * tn2);
    }
}

// ---------------------------------------------------------------------------
// Kernel 2: 512 blocks x 256 threads (fused lse + final mean via atomicAdd).
//   block b in [0,256):   image CE term  lse(logits[b, 0:264]) - logits[b,b]
//   block 256+a:          text  CE term  lse(logits[0:256, a]) - logits[a,a]
// ---------------------------------------------------------------------------
__global__ __launch_bounds__(256) void cl_lse_kernel(float* __restrict__ out)
{
    __shared__ float sd[256];
    int bid = blockIdx.x;
    int t   = threadIdx.x;

    float v1, v2 = -1e30f;
    float diag;
    if (bid < BS) {
        int b = bid;
        v1 = g_logits[b * ATN + t];
        if (t < ATN - BS) v2 = g_logits[b * ATN + BS + t];
        diag = g_logits[b * ATN + b];
    } else {
        int a = bid - BS;
        v1 = g_logits[t * ATN + a];
        diag = g_logits[a * ATN + a];
    }

    // block max
    sd[t] = fmaxf(v1, v2);
    __syncthreads();
    #pragma unroll
    for (int s = 128; s > 0; s >>= 1) {
        if (t < s) sd[t] = fmaxf(sd[t], sd[t + s]);
        __syncthreads();
    }
    float m = sd[0];
    __syncthreads();

    // block sum of exp
    sd[t] = expf(v1 - m) + expf(v2 - m);   // exp(-1e30 - m) == 0 for inactive slots
    __syncthreads();
    #pragma unroll
    for (int s = 128; s > 0; s >>= 1) {
        if (t < s) sd[t] += sd[t + s];
        __syncthreads();
    }
    if (t == 0) {
        float term = m + logf(sd[0]) - diag;
        atomicAdd(out, term * (1.0f / (2.0f * BS)));
    }
}

extern "C" void kernel_launch(void* const* d_in, const int* in_sizes, int n_in,
                              void* d_out, int out_size)
{
    const float* img     = (const float*)d_in[0];  // [256, 264, 512]
    const float* rand_t  = (const float*)d_in[1];  // [256, 512]
    const float* false_t = (const float*)d_in[2];  // [2048, 512]
    const float* lscale  = (const float*)d_in[3];  // [1]
    float* out = (float*)d_out;

    const int nwarps = BS * ATN;             // 67584
    const int tpb = 256;
    const int nblocks = (nwarps * 32 + tpb - 1) / tpb;  // 8448

    cl_dot_kernel<<<nblocks, tpb>>>(img, rand_t, false_t, lscale, out);
    cl_lse_kernel<<<2 * BS, 256>>>(out);
}